// round 2
// baseline (speedup 1.0000x reference)
#include <cuda_runtime.h>
#include <math.h>

#define NB 128
#define NT 30
#define NG 13
#define NC 16
#define NCELLS 169
#define ROWLEN 21
#define ROWS_FULL 10647
#define ELEMS 10647          // 507*21 used floats per batch
#define NSPLIT 4
#define CHUNK 2662           // ceil(10647/4)
#define NITER 11             // ceil(2662/256)

__device__ __forceinline__ float warp_sum(float v) {
    #pragma unroll
    for (int o = 16; o > 0; o >>= 1) v += __shfl_down_sync(0xffffffffu, v, o);
    return v;
}

__global__ void zero_kernel(float* out) {
    if (threadIdx.x == 0) out[0] = 0.0f;
}

__global__ void __launch_bounds__(256) region_loss_kernel(
    const float* __restrict__ outp,   // (128, 10647, 21)
    const float* __restrict__ tgt,    // (128, 30, 5)
    float* __restrict__ loss)
{
    const int b     = blockIdx.x;
    const int split = blockIdx.y;
    const int tid   = threadIdx.x;

    __shared__ int   s_cell2t[NCELLS];
    __shared__ int   s_idx[NT];
    __shared__ float s_x1[NT], s_y1[NT], s_x2[NT], s_y2[NT];
    __shared__ float s_locx[NT], s_locy[NT], s_tw[NT], s_th[NT], s_k[NT];
    __shared__ int   s_cls[NT];
    __shared__ float s_iou[NT][3];
    __shared__ int   s_maxa[NT];
    __shared__ float s_maxiou[NT];
    __shared__ float s_warp[8];

    for (int i = tid; i < NCELLS; i += blockDim.x) s_cell2t[i] = -1;

    // ---- Phase 2 loads issued FIRST (independent of the target tables) ----
    const size_t base  = (size_t)b * ((size_t)ROWS_FULL * ROWLEN);
    const int    start = split * CHUNK;
    const int    end   = (start + CHUNK < ELEMS) ? start + CHUNK : ELEMS;
    float v[NITER];
    #pragma unroll
    for (int i = 0; i < NITER; i++) {
        const int e = start + tid + i * 256;
        v[i] = (e < end) ? __ldg(outp + base + e) : 0.0f;
    }

    // ---- Phase 1A: targets (30 threads) ----
    if (tid < NT) {
        const float* tg = tgt + ((size_t)b * NT + tid) * 5;
        const float x1 = tg[0], y1 = tg[1], x2 = tg[2], y2 = tg[3];
        const float lx = (x1 + x2) * 0.5f;
        const float ly = (y1 + y2) * 0.5f;
        const int idx = (int)floorf(ly / 32.0f) * NG + (int)floorf(lx / 32.0f);
        const float tw = x2 - x1, th = y2 - y1;
        const float INVW = 1.0f / 416.0f;
        s_x1[tid] = x1; s_y1[tid] = y1; s_x2[tid] = x2; s_y2[tid] = y2;
        s_locx[tid] = lx; s_locy[tid] = ly;
        s_tw[tid] = tw; s_th[tid] = th;
        s_k[tid]  = (2.0f - (tw * INVW) * (th * INVW)) * INVW;
        s_cls[tid] = (int)tg[4];
        s_idx[tid] = idx;
        s_cell2t[idx] = tid;
    }
    __syncthreads();

    // ---- Phase 1B: IoU per (target, anchor) — 90 threads ----
    if (tid < NT * 3) {
        const int t = tid / 3;
        const int a = tid - t * 3;
        const int idx = s_idx[t];
        const float* p = outp + base + ((size_t)idx * 3 + a) * ROWLEN;
        const float px = p[0], py = p[1], pw = p[2], ph = p[3];
        const float bx1 = px - pw * 0.5f, by1 = py - ph * 0.5f;
        const float bx2 = px + pw * 0.5f, by2 = py + ph * 0.5f;
        const float x1 = s_x1[t], y1 = s_y1[t], x2 = s_x2[t], y2 = s_y2[t];
        const float ix1 = fmaxf(bx1, x1), iy1 = fmaxf(by1, y1);
        const float ix2 = fminf(bx2, x2), iy2 = fminf(by2, y2);
        const float inter = fmaxf(ix2 - ix1, 0.0f) * fmaxf(iy2 - iy1, 0.0f);
        const float a1 = (bx2 - bx1) * (by2 - by1);
        const float a2 = (x2 - x1) * (y2 - y1);
        s_iou[t][a] = inter / (a1 + a2 - inter + 1e-16f);
    }
    __syncthreads();

    // ---- Phase 1C: argmax over anchors (first-max semantics) ----
    if (tid < NT) {
        float best = -INFINITY;
        int best_a = 0;
        #pragma unroll
        for (int a = 0; a < 3; a++) {
            const float iou = s_iou[tid][a];
            if (iou > best) { best = iou; best_a = a; }
        }
        s_maxa[tid]   = best_a;
        s_maxiou[tid] = best;
    }
    __syncthreads();

    // ---- Phase 2: classify every element ----
    const float SQRT5 = 2.2360679774997896f;
    float acc = 0.0f;
    #pragma unroll
    for (int i = 0; i < NITER; i++) {
        const int e = start + tid + i * 256;
        if (e < end) {
            const unsigned ue = (unsigned)e;
            const unsigned j  = ue / 21u;          // anchor row
            const unsigned c  = ue - j * 21u;      // component
            const unsigned cell = j / 3u;
            const unsigned a    = j - cell * 3u;
            const int t = s_cell2t[cell];
            const float val = v[i];
            if (t < 0) {
                if (c == 4u) acc += val * val;
            } else {
                const bool am = ((int)a == s_maxa[t]);
                if (c == 4u) {
                    const float cm = am ? SQRT5 : (s_iou[t][a] > 0.5f ? 0.0f : 1.0f);
                    const float tc = am ? s_maxiou[t] : 0.0f;
                    const float d  = (val - tc) * cm;
                    acc += d * d;
                } else if (am) {
                    if (c < 4u) {
                        const float tv = (c == 0u) ? s_locx[t]
                                       : (c == 1u) ? s_locy[t]
                                       : (c == 2u) ? s_tw[t] : s_th[t];
                        const float d = (val - tv) * s_k[t];
                        acc += d * d;
                    } else {
                        const float d = val - (((int)c - 5 == s_cls[t]) ? 1.0f : 0.0f);
                        acc += d * d;
                    }
                }
            }
        }
    }
    acc *= 0.5f;

    // ---- Block reduction + single atomic ----
    acc = warp_sum(acc);
    const int lane = tid & 31, wid = tid >> 5;
    if (lane == 0) s_warp[wid] = acc;
    __syncthreads();
    if (wid == 0) {
        float x = (lane < 8) ? s_warp[lane] : 0.0f;
        x = warp_sum(x);
        if (lane == 0) atomicAdd(loss, x);
    }
}

extern "C" void kernel_launch(void* const* d_in, const int* in_sizes, int n_in,
                              void* d_out, int out_size) {
    const float* outp = (const float*)d_in[0];
    const float* tgt  = (const float*)d_in[1];
    float* loss = (float*)d_out;
    zero_kernel<<<1, 32>>>(loss);
    region_loss_kernel<<<dim3(NB, NSPLIT), 256>>>(outp, tgt, loss);
}

// round 3
// speedup vs baseline: 1.1964x; 1.1964x over previous
#include <cuda_runtime.h>
#include <math.h>

#define NB 128
#define NT 30
#define NG 13
#define NC 16
#define NCELLS 169
#define NROWS 507            // 169*3 anchor rows used per batch
#define ROWLEN 21
#define ROWS_FULL 10647

__device__ float    g_acc   = 0.0f;
__device__ unsigned g_count = 0u;

__device__ __forceinline__ float warp_sum(float v) {
    #pragma unroll
    for (int o = 16; o > 0; o >>= 1) v += __shfl_down_sync(0xffffffffu, v, o);
    return v;
}

__global__ void __launch_bounds__(512) region_loss_kernel(
    const float* __restrict__ outp,   // (128, 10647, 21)
    const float* __restrict__ tgt,    // (128, 30, 5)
    float* __restrict__ loss)
{
    const int b   = blockIdx.x;
    const int tid = threadIdx.x;
    const size_t base = (size_t)b * ((size_t)ROWS_FULL * ROWLEN);

    __shared__ float s_tgt[NT * 5];
    __shared__ int   s_cell2t[NCELLS];
    __shared__ int   s_idx[NT];
    __shared__ float s_x1[NT], s_y1[NT], s_x2[NT], s_y2[NT];
    __shared__ float s_locx[NT], s_locy[NT], s_tw[NT], s_th[NT], s_k[NT];
    __shared__ int   s_cls[NT];
    __shared__ float s_iou[NT][3];
    __shared__ float s_coord[NT][3];
    __shared__ float s_clsl[NT][3];
    __shared__ int   s_maxa[NT];
    __shared__ float s_maxiou[NT];
    __shared__ float s_warp[16];

    // ---- independent loads issued immediately ----
    float conf = 0.0f;
    if (tid < NROWS)  conf = __ldg(outp + base + (size_t)tid * ROWLEN + 4);
    if (tid < NT * 5) s_tgt[tid] = __ldg(tgt + (size_t)b * (NT * 5) + tid);
    if (tid < NCELLS) s_cell2t[tid] = -1;
    __syncthreads();

    // ---- per-target scalars (30 threads) ----
    if (tid < NT) {
        const float x1 = s_tgt[tid*5+0], y1 = s_tgt[tid*5+1];
        const float x2 = s_tgt[tid*5+2], y2 = s_tgt[tid*5+3];
        const float lx = (x1 + x2) * 0.5f;
        const float ly = (y1 + y2) * 0.5f;
        const int idx = (int)floorf(ly / 32.0f) * NG + (int)floorf(lx / 32.0f);
        const float tw = x2 - x1, th = y2 - y1;
        const float INVW = 1.0f / 416.0f;
        s_x1[tid] = x1; s_y1[tid] = y1; s_x2[tid] = x2; s_y2[tid] = y2;
        s_locx[tid] = lx; s_locy[tid] = ly;
        s_tw[tid] = tw;  s_th[tid] = th;
        s_k[tid]  = (2.0f - (tw * INVW) * (th * INVW)) * INVW;
        s_cls[tid] = (int)s_tgt[tid*5+4];
        s_idx[tid] = idx;
        s_cell2t[idx] = tid;
    }
    __syncthreads();

    // ---- per (target, anchor): IoU + coord loss + class loss (90 threads) ----
    if (tid < NT * 3) {
        const int t = tid / 3;
        const int a = tid - t * 3;
        const float* p = outp + base + ((size_t)s_idx[t] * 3 + a) * ROWLEN;
        const float px = p[0], py = p[1], pw = p[2], ph = p[3];

        // IoU (exact reference formula)
        const float bx1 = px - pw * 0.5f, by1 = py - ph * 0.5f;
        const float bx2 = px + pw * 0.5f, by2 = py + ph * 0.5f;
        const float x1 = s_x1[t], y1 = s_y1[t], x2 = s_x2[t], y2 = s_y2[t];
        const float ix1 = fmaxf(bx1, x1), iy1 = fmaxf(by1, y1);
        const float ix2 = fminf(bx2, x2), iy2 = fminf(by2, y2);
        const float inter = fmaxf(ix2 - ix1, 0.0f) * fmaxf(iy2 - iy1, 0.0f);
        const float a1 = (bx2 - bx1) * (by2 - by1);
        const float a2 = (x2 - x1) * (y2 - y1);
        s_iou[t][a] = inter / (a1 + a2 - inter + 1e-16f);

        // coord loss for this (t, a) — only selected if a == argmax
        const float k  = s_k[t];
        const float dx = (px - s_locx[t]) * k;
        const float dy = (py - s_locy[t]) * k;
        const float dw = (pw - s_tw[t])   * k;
        const float dh = (ph - s_th[t])   * k;
        s_coord[t][a] = dx*dx + dy*dy + dw*dw + dh*dh;

        // class loss for this (t, a)
        const int c0 = s_cls[t];
        float cs = 0.0f;
        #pragma unroll
        for (int c = 0; c < NC; c++) {
            const float d = p[5 + c] - (c == c0 ? 1.0f : 0.0f);
            cs += d * d;
        }
        s_clsl[t][a] = cs;
    }
    __syncthreads();

    // ---- argmax over anchors (first-max semantics) ----
    if (tid < NT) {
        float best = -INFINITY;
        int best_a = 0;
        #pragma unroll
        for (int a = 0; a < 3; a++) {
            const float iou = s_iou[tid][a];
            if (iou > best) { best = iou; best_a = a; }
        }
        s_maxa[tid]   = best_a;
        s_maxiou[tid] = best;
    }
    __syncthreads();

    // ---- per-row loss ----
    const float SQRT5 = 2.2360679774997896f;
    float acc = 0.0f;
    if (tid < NROWS) {
        const int cell = tid / 3;
        const int a    = tid - cell * 3;
        const int t    = s_cell2t[cell];
        if (t < 0) {
            acc = conf * conf;
        } else if (a == s_maxa[t]) {
            const float d = (conf - s_maxiou[t]) * SQRT5;
            acc = d * d + s_coord[t][a] + s_clsl[t][a];
        } else {
            const float cm = (s_iou[t][a] > 0.5f) ? 0.0f : 1.0f;
            const float d  = conf * cm;
            acc = d * d;
        }
    }
    acc *= 0.5f;

    // ---- block reduce (16 warps) ----
    acc = warp_sum(acc);
    const int lane = tid & 31, wid = tid >> 5;
    if (lane == 0) s_warp[wid] = acc;
    __syncthreads();
    if (wid == 0) {
        float x = (lane < 16) ? s_warp[lane] : 0.0f;
        x = warp_sum(x);
        if (lane == 0) {
            atomicAdd(&g_acc, x);
            __threadfence();
            const unsigned old = atomicAdd(&g_count, 1u);
            if (old == (unsigned)(gridDim.x - 1)) {
                // last block: publish result and reset scratch for next replay
                const float total = atomicAdd(&g_acc, 0.0f);
                loss[0] = total;
                atomicExch(&g_acc, 0.0f);
                atomicExch(&g_count, 0u);
            }
        }
    }
}

extern "C" void kernel_launch(void* const* d_in, const int* in_sizes, int n_in,
                              void* d_out, int out_size) {
    const float* outp = (const float*)d_in[0];
    const float* tgt  = (const float*)d_in[1];
    float* loss = (float*)d_out;
    region_loss_kernel<<<NB, 512>>>(outp, tgt, loss);
}

// round 4
// speedup vs baseline: 1.2362x; 1.0332x over previous
#include <cuda_runtime.h>
#include <math.h>

#define NB 128
#define NT 30
#define NG 13
#define NC 16
#define NCELLS 169
#define NROWS 507            // 169*3 anchor rows used per batch
#define ROWLEN 21
#define ROWS_FULL 10647
#define PSTRIDE 22           // padded row stride in smem

__device__ __forceinline__ float warp_sum(float v) {
    #pragma unroll
    for (int o = 16; o > 0; o >>= 1) v += __shfl_down_sync(0xffffffffu, v, o);
    return v;
}

__global__ void zero_kernel(float* out) {
    if (threadIdx.x == 0) out[0] = 0.0f;
}

__global__ void __launch_bounds__(512) region_loss_kernel(
    const float* __restrict__ outp,   // (128, 10647, 21)
    const float* __restrict__ tgt,    // (128, 30, 5)
    float* __restrict__ loss)
{
    const int b   = blockIdx.x;
    const int tid = threadIdx.x;
    const size_t base = (size_t)b * ((size_t)ROWS_FULL * ROWLEN);

    __shared__ float s_tgt[NT * 5];
    __shared__ int   s_cell2t[NCELLS];
    __shared__ float s_p[90 * PSTRIDE];      // staged target rows
    __shared__ float s_locx[NT], s_locy[NT], s_tw[NT], s_th[NT], s_k[NT];
    __shared__ int   s_cls[NT];
    __shared__ float s_iou[NT][3];
    __shared__ float s_extra[NT][3];         // coord+class loss per (t,a)
    __shared__ float s_warp[16];

    // ---- phase 0: independent global loads issued immediately ----
    float conf = 0.0f;
    if (tid < NROWS)  conf = __ldg(outp + base + (size_t)tid * ROWLEN + 4);
    if (tid < NT * 5) s_tgt[tid] = __ldg(tgt + (size_t)b * (NT * 5) + tid);
    if (tid < NCELLS) s_cell2t[tid] = -1;
    __syncthreads();   // s_tgt + cell2t init visible

    // ---- phase 1: staged row gather (row-parallel, coalesced-ish) ----
    // 21 consecutive threads load one row's 21 floats. 24 rows per pass, 4 passes.
    {
        const int r0  = tid / ROWLEN;        // 0..24 (tid<504)
        const int col = tid - r0 * ROWLEN;   // 0..20
        #pragma unroll
        for (int it = 0; it < 4; it++) {
            const int row = it * 24 + r0;
            if (tid < 504 && row < 90) {
                const int t = row / 3;
                const int a = row - t * 3;
                const float lx = (s_tgt[t*5+0] + s_tgt[t*5+2]) * 0.5f;
                const float ly = (s_tgt[t*5+1] + s_tgt[t*5+3]) * 0.5f;
                const int idx = (int)floorf(ly / 32.0f) * NG + (int)floorf(lx / 32.0f);
                s_p[row * PSTRIDE + col] =
                    __ldg(outp + base + ((size_t)idx * 3 + a) * ROWLEN + col);
            }
        }
    }
    // ---- concurrent: per-target scalars (30 threads, reads only s_tgt) ----
    if (tid < NT) {
        const float x1 = s_tgt[tid*5+0], y1 = s_tgt[tid*5+1];
        const float x2 = s_tgt[tid*5+2], y2 = s_tgt[tid*5+3];
        const float lx = (x1 + x2) * 0.5f;
        const float ly = (y1 + y2) * 0.5f;
        const int idx = (int)floorf(ly / 32.0f) * NG + (int)floorf(lx / 32.0f);
        const float tw = x2 - x1, th = y2 - y1;
        const float INVW = 1.0f / 416.0f;
        s_locx[tid] = lx; s_locy[tid] = ly;
        s_tw[tid] = tw;  s_th[tid] = th;
        s_k[tid]  = (2.0f - (tw * INVW) * (th * INVW)) * INVW;
        s_cls[tid] = (int)s_tgt[tid*5+4];
        s_cell2t[idx] = tid;
    }
    __syncthreads();   // s_p + scalar tables visible

    // ---- phase 2: per (t,a) IoU + coord + class loss (90 threads, smem only) ----
    if (tid < NT * 3) {
        const int t = tid / 3;
        const int a = tid - t * 3;
        const float* p = s_p + tid * PSTRIDE;
        const float px = p[0], py = p[1], pw = p[2], ph = p[3];

        const float bx1 = px - pw * 0.5f, by1 = py - ph * 0.5f;
        const float bx2 = px + pw * 0.5f, by2 = py + ph * 0.5f;
        const float x1 = s_tgt[t*5+0], y1 = s_tgt[t*5+1];
        const float x2 = s_tgt[t*5+2], y2 = s_tgt[t*5+3];
        const float ix1 = fmaxf(bx1, x1), iy1 = fmaxf(by1, y1);
        const float ix2 = fminf(bx2, x2), iy2 = fminf(by2, y2);
        const float inter = fmaxf(ix2 - ix1, 0.0f) * fmaxf(iy2 - iy1, 0.0f);
        const float a1 = (bx2 - bx1) * (by2 - by1);
        const float a2 = (x2 - x1) * (y2 - y1);
        s_iou[t][a] = inter / (a1 + a2 - inter + 1e-16f);

        // coord loss
        const float k  = s_k[t];
        const float dx = (px - s_locx[t]) * k;
        const float dy = (py - s_locy[t]) * k;
        const float dw = (pw - s_tw[t])   * k;
        const float dh = (ph - s_th[t])   * k;
        float ex = dx*dx + dy*dy + dw*dw + dh*dh;

        // class loss
        const int c0 = s_cls[t];
        #pragma unroll
        for (int c = 0; c < NC; c++) {
            const float d = p[5 + c] - (c == c0 ? 1.0f : 0.0f);
            ex += d * d;
        }
        s_extra[t][a] = ex;
    }
    __syncthreads();   // iou/extra tables visible

    // ---- phase 3: per-row loss (argmax recomputed locally; first-max) ----
    const float SQRT5 = 2.2360679774997896f;
    float acc = 0.0f;
    if (tid < NROWS) {
        const int cell = tid / 3;
        const int a    = tid - cell * 3;
        const int t    = s_cell2t[cell];
        if (t < 0) {
            acc = conf * conf;
        } else {
            const float i0 = s_iou[t][0], i1 = s_iou[t][1], i2 = s_iou[t][2];
            float best = i0; int best_a = 0;
            if (i1 > best) { best = i1; best_a = 1; }
            if (i2 > best) { best = i2; best_a = 2; }
            if (a == best_a) {
                const float d = (conf - best) * SQRT5;
                acc = d * d + s_extra[t][a];
            } else {
                const float ia = (a == 0) ? i0 : (a == 1) ? i1 : i2;
                const float cm = (ia > 0.5f) ? 0.0f : 1.0f;
                const float d  = conf * cm;
                acc = d * d;
            }
        }
    }
    acc *= 0.5f;

    // ---- block reduce, then single fire-and-forget atomic (REDG) ----
    acc = warp_sum(acc);
    const int lane = tid & 31, wid = tid >> 5;
    if (lane == 0) s_warp[wid] = acc;
    __syncthreads();
    if (wid == 0) {
        float x = (lane < 16) ? s_warp[lane] : 0.0f;
        x = warp_sum(x);
        if (lane == 0) atomicAdd(loss, x);   // result unused -> RED, no wait
    }
}

extern "C" void kernel_launch(void* const* d_in, const int* in_sizes, int n_in,
                              void* d_out, int out_size) {
    const float* outp = (const float*)d_in[0];
    const float* tgt  = (const float*)d_in[1];
    float* loss = (float*)d_out;
    zero_kernel<<<1, 32>>>(loss);
    region_loss_kernel<<<NB, 512>>>(outp, tgt, loss);
}